// round 13
// baseline (speedup 1.0000x reference)
#include <cuda_runtime.h>

#define NODES 7
#define CH 256
#define PAIRS 128
#define HID 128
#define P_TOTAL 65536
#define PF 8                    // prefetch depth (channel pairs per half)

typedef unsigned long long ull;

__device__ float g_nw[2 * NODES * CH];              // new_weight [b, n, c]
__device__ float g_attn8[2 * P_TOTAL * 8];          // attn interleaved [b][p][8] (4MB)

// ---------------------------------------------------------------------------
__device__ __forceinline__ ull fma2(ull a, ull b, ull c) {
    ull d;
    asm("fma.rn.f32x2 %0, %1, %2, %3;" : "=l"(d) : "l"(a), "l"(b), "l"(c));
    return d;
}
__device__ __forceinline__ ull pack2(float x, float y) {
    ull r;
    asm("mov.b64 %0, {%1, %2};" : "=l"(r) : "f"(x), "f"(y));
    return r;
}
__device__ __forceinline__ void unpack2(ull v, float& x, float& y) {
    asm("mov.b64 {%0, %1}, %2;" : "=f"(x), "=f"(y) : "l"(v));
}
__device__ __forceinline__ float ldcs32(const float* p) {
    float v;
    asm volatile("ld.global.cs.b32 %0, [%1];" : "=f"(v) : "l"(p));
    return v;
}
__device__ __forceinline__ void stcs64(float* p, ull v) {
    asm volatile("st.global.cs.b64 [%0], %1;" :: "l"(p), "l"(v));
}
__device__ __forceinline__ void st128(float* p, float4 v) {
    asm volatile("st.global.v4.f32 [%0], {%1,%2,%3,%4};"
                 :: "l"(p), "f"(v.x), "f"(v.y), "f"(v.z), "f"(v.w));
}
__device__ __forceinline__ float4 ld128(const float* p) {
    float4 v;
    asm volatile("ld.global.v4.f32 {%0,%1,%2,%3}, [%4];"
                 : "=f"(v.x), "=f"(v.y), "=f"(v.z), "=f"(v.w) : "l"(p));
    return v;
}

// ---------------------------------------------------------------------------
// Pass 1: PURE READ stream. res (128MB) -> n1 -> softmax -> g_attn8.
// 2-way channel split: half h covers channels [128h, 128h+128) of one point.
// Blocks 0..1023 stream; blocks 1024..1037 compute the g_nw GEMM.
// ---------------------------------------------------------------------------
__global__ void __launch_bounds__(256, 4) pass1_kernel(
    const float* __restrict__ inp,     // [1,2,7,128]
    const float* __restrict__ res,     // [2, 256, 65536]
    const float* __restrict__ Wres,    // [256, 7]
    const float* __restrict__ nfh,     // [128,1]
    const float* __restrict__ weight)  // [128, 256]
{
    const int tid = threadIdx.x;
    const int bid = blockIdx.x;

    // ---- tail blocks: new_weight GEMM ----
    if (bid >= 1024) {
        const int bn = bid - 1024;       // 0..13 = b*7+n
        float acc = 0.f;
#pragma unroll 16
        for (int h = 0; h < HID; ++h)
            acc += __ldg(inp + bn * HID + h) * weight[h * CH + tid];
        g_nw[bn * CH + tid] = acc;
        return;
    }

    __shared__ ull W2[PAIRS][8];          // (w[2k][n], w[2k+1][n])
    __shared__ float part[NODES][2][128]; // cross-half partials
    __shared__ float sh_n2[8];

    const int half = tid >> 7;           // channel half
    const int pl   = tid & 127;
    const int b    = bid >> 9;           // 0..1
    const int tile = bid & 511;
    const int p    = tile * 128 + pl;
    const int wid  = tid >> 5;
    const int lane = tid & 31;

    // n2[b][n]: warp n computes the 128-dot via shuffle
    if (wid < NODES) {
        float s = 0.f;
#pragma unroll
        for (int i = 0; i < 4; ++i) {
            int h = lane + 32 * i;
            s += __ldg(inp + b * NODES * HID + wid * HID + h) * __ldg(nfh + h);
        }
#pragma unroll
        for (int o = 16; o; o >>= 1)
            s += __shfl_xor_sync(0xffffffffu, s, o);
        if (lane == 0) sh_n2[wid] = s;
    }
    if (tid < PAIRS) {
        const int k = tid;
#pragma unroll
        for (int n = 0; n < NODES; ++n) {
            float w0 = Wres[(2 * k) * NODES + n];
            float w1 = Wres[(2 * k + 1) * NODES + n];
            W2[k][n] = pack2(w0, w1);
        }
        W2[k][7] = 0ull;
    }
    __syncthreads();

    float n2s[NODES];
#pragma unroll
    for (int n = 0; n < NODES; ++n) n2s[n] = sh_n2[n];

    const int kbase = half * 64;
    const float* rfp = res + (size_t)b * CH * P_TOTAL
                           + (size_t)(half * 128) * P_TOTAL + p;

    ull acc[NODES];
#pragma unroll
    for (int n = 0; n < NODES; ++n) acc[n] = 0ull;

    float a0[PF], a1[PF];
#pragma unroll
    for (int i = 0; i < PF; ++i) {
        a0[i] = ldcs32(rfp + (size_t)(2 * i) * P_TOTAL);
        a1[i] = ldcs32(rfp + (size_t)(2 * i + 1) * P_TOTAL);
    }

#pragma unroll 1
    for (int jb = 0; jb < 64; jb += PF) {
#pragma unroll
        for (int i = 0; i < PF; ++i) {
            ull v = pack2(a0[i], a1[i]);
            if (jb + PF < 64) {
                a0[i] = ldcs32(rfp + (size_t)(2 * (jb + PF + i)) * P_TOTAL);
                a1[i] = ldcs32(rfp + (size_t)(2 * (jb + PF + i) + 1) * P_TOTAL);
            }
            const ulonglong2* wr = (const ulonglong2*)(&W2[kbase + jb + i][0]);
            ulonglong2 w01 = wr[0];
            ulonglong2 w23 = wr[1];
            ulonglong2 w45 = wr[2];
            ulonglong2 w6p = wr[3];
            acc[0] = fma2(v, w01.x, acc[0]);
            acc[1] = fma2(v, w01.y, acc[1]);
            acc[2] = fma2(v, w23.x, acc[2]);
            acc[3] = fma2(v, w23.y, acc[3]);
            acc[4] = fma2(v, w45.x, acc[4]);
            acc[5] = fma2(v, w45.y, acc[5]);
            acc[6] = fma2(v, w6p.x, acc[6]);
        }
    }

    // Exchange partials between halves
    float myp[NODES];
#pragma unroll
    for (int n = 0; n < NODES; ++n) {
        float lo, hi;
        unpack2(acc[n], lo, hi);
        myp[n] = lo + hi;
        part[n][half][pl] = myp[n];
    }
    __syncthreads();

    float s[NODES];
#pragma unroll
    for (int n = 0; n < NODES; ++n)
        s[n] = myp[n] + part[n][half ^ 1][pl] + n2s[n];

    float m = s[0];
#pragma unroll
    for (int n = 1; n < NODES; ++n) m = fmaxf(m, s[n]);
    float e[NODES], sum = 0.f;
#pragma unroll
    for (int n = 0; n < NODES; ++n) { e[n] = __expf(s[n] - m); sum += e[n]; }
    float inv = __fdividef(1.f, sum);

    // Interleaved attn store: one STG.128 per thread.
    //   half0 writes attn[p][0..3], half1 writes attn[p][4..7] (slot 7 = pad).
    float* ap = g_attn8 + ((size_t)b * P_TOTAL + p) * 8 + half * 4;
    float4 av;
    if (half == 0) {
        av.x = e[0] * inv; av.y = e[1] * inv; av.z = e[2] * inv; av.w = e[3] * inv;
    } else {
        av.x = e[4] * inv; av.y = e[5] * inv; av.z = e[6] * inv; av.w = 0.f;
    }
    st128(ap, av);
}

// ---------------------------------------------------------------------------
// Pass 2: PURE WRITE stream (PDL-overlapped). g_attn8 (L2) + g_nw -> out.
// 2 points/thread, 256 blocks x 256 threads.
// ---------------------------------------------------------------------------
__global__ void __launch_bounds__(256, 6) pass2_kernel(
    float* __restrict__ out)           // [2, 256, 65536]
{
    cudaGridDependencySynchronize();   // PDL: wait for pass1's memory

    __shared__ ull NW[CH][8];

    const int tid  = threadIdx.x;
    const int b    = blockIdx.x >> 7;
    const int tile = blockIdx.x & 127;

    {
        const int c = tid;
#pragma unroll
        for (int n = 0; n < NODES; ++n) {
            float q = g_nw[(b * NODES + n) * CH + c];
            NW[c][n] = pack2(q, q);
        }
        NW[c][7] = 0ull;
    }
    __syncthreads();

    const int p0 = tile * 512 + 2 * tid;

    // attn for both points: 16 contiguous floats = 4 LDG.128 (L2 hits)
    const float* ap = g_attn8 + ((size_t)b * P_TOTAL + p0) * 8;
    float4 q0a = ld128(ap + 0);    // p0 attn[0..3]
    float4 q0b = ld128(ap + 4);    // p0 attn[4..7]
    float4 q1a = ld128(ap + 8);    // p1 attn[0..3]
    float4 q1b = ld128(ap + 12);   // p1 attn[4..7]

    ull at[NODES];
    at[0] = pack2(q0a.x, q1a.x);
    at[1] = pack2(q0a.y, q1a.y);
    at[2] = pack2(q0a.z, q1a.z);
    at[3] = pack2(q0a.w, q1a.w);
    at[4] = pack2(q0b.x, q1b.x);
    at[5] = pack2(q0b.y, q1b.y);
    at[6] = pack2(q0b.z, q1b.z);

    float* op = out + (size_t)b * CH * P_TOTAL + p0;
#pragma unroll 4
    for (int c = 0; c < CH; ++c) {
        const ulonglong2* nr = (const ulonglong2*)(&NW[c][0]);
        ulonglong2 q01 = nr[0];
        ulonglong2 q23 = nr[1];
        ulonglong2 q45 = nr[2];
        ulonglong2 q6p = nr[3];
        ull o = 0ull;
        o = fma2(at[0], q01.x, o);
        o = fma2(at[1], q01.y, o);
        o = fma2(at[2], q23.x, o);
        o = fma2(at[3], q23.y, o);
        o = fma2(at[4], q45.x, o);
        o = fma2(at[5], q45.y, o);
        o = fma2(at[6], q6p.x, o);
        float v0, v1;
        unpack2(o, v0, v1);
        stcs64(op + (size_t)c * P_TOTAL, pack2(fmaxf(v0, 0.f), fmaxf(v1, 0.f)));
    }
}

// ---------------------------------------------------------------------------
extern "C" void kernel_launch(void* const* d_in, const int* in_sizes, int n_in,
                              void* d_out, int out_size) {
    const float* inp    = (const float*)d_in[0];  // [1,2,7,128]
    const float* res    = (const float*)d_in[1];  // [2,256,16,64,64]
    const float* Wres   = (const float*)d_in[2];  // [256,7]
    const float* nfh    = (const float*)d_in[3];  // [128,1]
    const float* weight = (const float*)d_in[4];  // [128,256]

    pass1_kernel<<<1038, 256>>>(inp, res, Wres, nfh, weight);

    // pass2 with Programmatic Dependent Launch: overlap its launch/prologue
    // with pass1's tail; cudaGridDependencySynchronize() inside guards data.
    cudaLaunchConfig_t cfg = {};
    cfg.gridDim  = dim3(256, 1, 1);
    cfg.blockDim = dim3(256, 1, 1);
    cudaLaunchAttribute attrs[1];
    attrs[0].id = cudaLaunchAttributeProgrammaticStreamSerialization;
    attrs[0].val.programmaticStreamSerializationAllowed = 1;
    cfg.attrs = attrs;
    cfg.numAttrs = 1;
    cudaLaunchKernelEx(&cfg, pass2_kernel, (float*)d_out);
}